// round 5
// baseline (speedup 1.0000x reference)
#include <cuda_runtime.h>

// out = y where 0 < y <= 1 else 0, y = x * w[col] + b[col]
// x: [8192, 4096] f32, w/b: [4096] f32. Pure HBM-bound elementwise.
// R5: R2 shape (flat grid, ITEMS=4, front-batched streaming loads) with
//     register cap for max occupancy; columns are compile-time offsets
//     t+{0,256,512,768} since chunk (1024) == D_VEC.

#define D_VEC 1024            // 4096/4
#define ITEMS 4
#define THREADS 256
#define CHUNK (THREADS * ITEMS)   // 1024 == D_VEC -> col(i) = t + i*256

__global__ void __launch_bounds__(THREADS, 8)   // force <=32 regs, occ 100%
gegate_kernel(const float4* __restrict__ x,
              const float4* __restrict__ w,
              const float4* __restrict__ b,
              float4* __restrict__ out)
{
    const int t = threadIdx.x;
    const int base = blockIdx.x * CHUNK + t;

    // Front-batched streaming reads: 4 independent DRAM loads in flight.
    float4 xv[ITEMS];
    #pragma unroll
    for (int i = 0; i < ITEMS; i++)
        xv[i] = __ldcs(&x[base + i * THREADS]);

    // Per item: col is a fixed offset (chunk == D_VEC). Load w/b just-in-time
    // (L2/L1-resident after first wave), compute, store — keeps live regs low.
    #pragma unroll
    for (int i = 0; i < ITEMS; i++) {
        const int col = t + i * THREADS;
        float4 wv = __ldg(&w[col]);
        float4 bv = __ldg(&b[col]);
        float4 y;
        y.x = fmaf(xv[i].x, wv.x, bv.x);
        y.y = fmaf(xv[i].y, wv.y, bv.y);
        y.z = fmaf(xv[i].z, wv.z, bv.z);
        y.w = fmaf(xv[i].w, wv.w, bv.w);
        y.x = (y.x > 0.0f && y.x <= 1.0f) ? y.x : 0.0f;
        y.y = (y.y > 0.0f && y.y <= 1.0f) ? y.y : 0.0f;
        y.z = (y.z > 0.0f && y.z <= 1.0f) ? y.z : 0.0f;
        y.w = (y.w > 0.0f && y.w <= 1.0f) ? y.w : 0.0f;
        __stcs(&out[base + i * THREADS], y);
    }
}

extern "C" void kernel_launch(void* const* d_in, const int* in_sizes, int n_in,
                              void* d_out, int out_size)
{
    const float4* x = (const float4*)d_in[0];
    const float4* w = (const float4*)d_in[1];
    const float4* b = (const float4*)d_in[2];
    float4* out = (float4*)d_out;

    int n_vec = out_size / 4;             // 8388608
    int blocks = n_vec / CHUNK;           // 8192 exactly

    gegate_kernel<<<blocks, THREADS>>>(x, w, b, out);
}

// round 6
// speedup vs baseline: 1.0234x; 1.0234x over previous
#include <cuda_runtime.h>

// out = y where 0 < y <= 1 else 0, y = x * w[col] + b[col]
// x: [8192, 4096] f32, w/b: [4096] f32. Pure HBM-bound elementwise.
// R6: R2 shape (flat grid, ITEMS=4, chunk==D_VEC) with ALL loads front-batched:
//     4 streaming x LDG.128 + 4 w + 4 b LDG.128 in flight before compute.
//     No reg cap (R5 showed capping hurts ptxas scheduling).

#define D_VEC 1024            // 4096/4
#define ITEMS 4
#define THREADS 256
#define CHUNK (THREADS * ITEMS)   // 1024 == D_VEC -> col(i) = t + i*256

__global__ void __launch_bounds__(THREADS)
gegate_kernel(const float4* __restrict__ x,
              const float4* __restrict__ w,
              const float4* __restrict__ b,
              float4* __restrict__ out)
{
    const int t = threadIdx.x;
    const int base = blockIdx.x * CHUNK + t;

    // Front-batch everything: 12 independent loads in the L1tex queue.
    float4 xv[ITEMS];
    #pragma unroll
    for (int i = 0; i < ITEMS; i++)
        xv[i] = __ldcs(&x[base + i * THREADS]);

    float4 wv[ITEMS], bv[ITEMS];
    #pragma unroll
    for (int i = 0; i < ITEMS; i++) {
        wv[i] = __ldg(&w[t + i * THREADS]);
        bv[i] = __ldg(&b[t + i * THREADS]);
    }

    // Compute + store (streaming stores, no L2 retention of out).
    #pragma unroll
    for (int i = 0; i < ITEMS; i++) {
        float4 y;
        y.x = fmaf(xv[i].x, wv[i].x, bv[i].x);
        y.y = fmaf(xv[i].y, wv[i].y, bv[i].y);
        y.z = fmaf(xv[i].z, wv[i].z, bv[i].z);
        y.w = fmaf(xv[i].w, wv[i].w, bv[i].w);
        y.x = (y.x > 0.0f && y.x <= 1.0f) ? y.x : 0.0f;
        y.y = (y.y > 0.0f && y.y <= 1.0f) ? y.y : 0.0f;
        y.z = (y.z > 0.0f && y.z <= 1.0f) ? y.z : 0.0f;
        y.w = (y.w > 0.0f && y.w <= 1.0f) ? y.w : 0.0f;
        __stcs(&out[base + i * THREADS], y);
    }
}

extern "C" void kernel_launch(void* const* d_in, const int* in_sizes, int n_in,
                              void* d_out, int out_size)
{
    const float4* x = (const float4*)d_in[0];
    const float4* w = (const float4*)d_in[1];
    const float4* b = (const float4*)d_in[2];
    float4* out = (float4*)d_out;

    int n_vec = out_size / 4;             // 8388608
    int blocks = n_vec / CHUNK;           // 8192 exactly

    gegate_kernel<<<blocks, THREADS>>>(x, w, b, out);
}